// round 1
// baseline (speedup 1.0000x reference)
#include <cuda_runtime.h>
#include <math.h>
#include <stdint.h>

#define D 128
#define MAXSRC 100000
#define MAXDST 50000

// Scratch (allocation-free rule: __device__ globals)
__device__ float g_a_src[MAXSRC * D];   // feat_src @ W1[:,128:256]^T
__device__ float g_a_dst[MAXDST * D];   // feat_dst @ W1[:,0:128]^T + b1
__device__ float g_neigh[MAXDST * D];   // sum_e ex * m   (unnormalized)
__device__ float g_denom[MAXDST];       // sum_e ex

// ---------------------------------------------------------------------------
// Zero the accumulators (must run every launch; graph replays).
// ---------------------------------------------------------------------------
__global__ void zero_kernel(int ndst) {
    int i = blockIdx.x * blockDim.x + threadIdx.x;
    int n4 = ndst * (D / 4);
    int d4 = ndst / 4;
    float4 z = make_float4(0.f, 0.f, 0.f, 0.f);
    if (i < n4) {
        ((float4*)g_neigh)[i] = z;
    } else if (i < n4 + d4) {
        ((float4*)g_denom)[i - n4] = z;
    }
}

// ---------------------------------------------------------------------------
// proj: Y[m][d] = (bias?bias[d]:0) + sum_k X[m][k] * W[d*wstride + woff + k]
// 256 threads, 64 rows/block. Dynamic smem: Wt[128*128] (k-major) + Xs[64*128].
// ---------------------------------------------------------------------------
__global__ void proj_kernel(const float* __restrict__ X,
                            const float* __restrict__ W,
                            const float* __restrict__ bias,
                            float* __restrict__ Y,
                            int M, int wstride, int woff) {
    extern __shared__ float sm[];
    float* Wt = sm;          // [k][d]  128*128
    float* Xs = sm + D * D;  // [r][k]  64*128
    const int tid = threadIdx.x;
    const int R = blockIdx.x * 64;

    // Load + transpose W tile (coalesced along k)
    for (int i = tid; i < D * 32; i += 256) {
        int d = i >> 5;
        int kq = i & 31;
        float4 w = *(const float4*)&W[(size_t)d * wstride + woff + 4 * kq];
        Wt[(4 * kq + 0) * D + d] = w.x;
        Wt[(4 * kq + 1) * D + d] = w.y;
        Wt[(4 * kq + 2) * D + d] = w.z;
        Wt[(4 * kq + 3) * D + d] = w.w;
    }
    // Load X tile
    for (int i = tid; i < 64 * 32; i += 256) {
        int r = i >> 5;
        int kq = i & 31;
        int row = R + r;
        float4 v = make_float4(0.f, 0.f, 0.f, 0.f);
        if (row < M) v = *(const float4*)&X[(size_t)row * D + 4 * kq];
        *(float4*)&Xs[r * D + 4 * kq] = v;
    }
    __syncthreads();

    const int c = tid & 31;   // 4-column group
    const int rg = tid >> 5;  // warp id = row-group (x loads broadcast in warp)
    float acc[8][4];
#pragma unroll
    for (int j = 0; j < 8; j++)
#pragma unroll
        for (int q = 0; q < 4; q++) acc[j][q] = 0.f;

#pragma unroll 4
    for (int k = 0; k < D; k++) {
        float4 w = *(float4*)&Wt[k * D + 4 * c];
#pragma unroll
        for (int j = 0; j < 8; j++) {
            float x = Xs[(rg + 8 * j) * D + k];
            acc[j][0] += x * w.x;
            acc[j][1] += x * w.y;
            acc[j][2] += x * w.z;
            acc[j][3] += x * w.w;
        }
    }

    float4 bv = make_float4(0.f, 0.f, 0.f, 0.f);
    if (bias) bv = *(const float4*)&bias[4 * c];
#pragma unroll
    for (int j = 0; j < 8; j++) {
        int row = R + rg + 8 * j;
        if (row < M) {
            float4 o = make_float4(acc[j][0] + bv.x, acc[j][1] + bv.y,
                                   acc[j][2] + bv.z, acc[j][3] + bv.w);
            *(float4*)&Y[(size_t)row * D + 4 * c] = o;
        }
    }
}

// ---------------------------------------------------------------------------
// Edge pass: one warp per edge.
//   score = W2 . tanh(a_dst[d] + a_src[s]);  ex = exp(score)
//   neigh[d] += ex * feat_src[s];  denom[d] += ex
// ---------------------------------------------------------------------------
__global__ void edge_kernel(const int* __restrict__ esrc,
                            const int* __restrict__ edst,
                            const float* __restrict__ feat_src,
                            const float* __restrict__ W2, int E) {
    __shared__ float w2s[D];
    const int lane = threadIdx.x & 31;
    const int wid = threadIdx.x >> 5;
    if (threadIdx.x < D) w2s[threadIdx.x] = W2[threadIdx.x];
    __syncthreads();

    int e = blockIdx.x * (blockDim.x >> 5) + wid;
    if (e >= E) return;

    const int s = esrc[e];
    const int d = edst[e];
    float4 a = ((const float4*)&g_a_dst[(size_t)d * D])[lane];
    float4 b = ((const float4*)&g_a_src[(size_t)s * D])[lane];
    float z0 = tanhf(a.x + b.x);
    float z1 = tanhf(a.y + b.y);
    float z2 = tanhf(a.z + b.z);
    float z3 = tanhf(a.w + b.w);
    float4 w2 = *(float4*)&w2s[4 * lane];
    float p = z0 * w2.x + z1 * w2.y + z2 * w2.z + z3 * w2.w;
#pragma unroll
    for (int o = 16; o > 0; o >>= 1) p += __shfl_xor_sync(0xFFFFFFFFu, p, o);
    float ex = __expf(p);

    float4 m = ((const float4*)&feat_src[(size_t)s * D])[lane];
    float* np = &g_neigh[(size_t)d * D + 4 * lane];
    asm volatile("red.global.add.v4.f32 [%0], {%1,%2,%3,%4};" ::"l"(np),
                 "f"(ex * m.x), "f"(ex * m.y), "f"(ex * m.z), "f"(ex * m.w)
                 : "memory");
    if (lane == 0) atomicAdd(&g_denom[d], ex);
}

// ---------------------------------------------------------------------------
// Output: out[n][d] = relu(bfc[d] + fd[n]@Wfc[d,0:128] + (neigh[n]/denom[n])@Wfc[d,128:256])
// Two k-phases reuse one 64KB Wt buffer. Denom-normalize folded into X load.
// ---------------------------------------------------------------------------
__global__ void out_kernel(const float* __restrict__ fdst,
                           const float* __restrict__ Wfc,
                           const float* __restrict__ bfc,
                           float* __restrict__ out, int M) {
    extern __shared__ float sm[];
    float* Wt = sm;          // [k][d] 128*128
    float* Xs = sm + D * D;  // [r][k] 64*128
    const int tid = threadIdx.x;
    const int R = blockIdx.x * 64;
    const int c = tid & 31;
    const int rg = tid >> 5;

    float acc[8][4];
#pragma unroll
    for (int j = 0; j < 8; j++)
#pragma unroll
        for (int q = 0; q < 4; q++) acc[j][q] = 0.f;

    for (int phase = 0; phase < 2; phase++) {
        if (phase) __syncthreads();  // WAR: previous compute done before overwrite
        for (int i = tid; i < D * 32; i += 256) {
            int d = i >> 5;
            int kq = i & 31;
            float4 w = *(const float4*)&Wfc[(size_t)d * 256 + phase * D + 4 * kq];
            Wt[(4 * kq + 0) * D + d] = w.x;
            Wt[(4 * kq + 1) * D + d] = w.y;
            Wt[(4 * kq + 2) * D + d] = w.z;
            Wt[(4 * kq + 3) * D + d] = w.w;
        }
        for (int i = tid; i < 64 * 32; i += 256) {
            int r = i >> 5;
            int kq = i & 31;
            int row = R + r;
            float4 v = make_float4(0.f, 0.f, 0.f, 0.f);
            if (row < M) {
                if (phase == 0) {
                    v = *(const float4*)&fdst[(size_t)row * D + 4 * kq];
                } else {
                    float dn = g_denom[row];
                    float inv = dn > 0.f ? 1.f / dn : 0.f;
                    float4 nr = *(const float4*)&g_neigh[(size_t)row * D + 4 * kq];
                    v = make_float4(nr.x * inv, nr.y * inv, nr.z * inv, nr.w * inv);
                }
            }
            *(float4*)&Xs[r * D + 4 * kq] = v;
        }
        __syncthreads();

#pragma unroll 4
        for (int k = 0; k < D; k++) {
            float4 w = *(float4*)&Wt[k * D + 4 * c];
#pragma unroll
            for (int j = 0; j < 8; j++) {
                float x = Xs[(rg + 8 * j) * D + k];
                acc[j][0] += x * w.x;
                acc[j][1] += x * w.y;
                acc[j][2] += x * w.z;
                acc[j][3] += x * w.w;
            }
        }
    }

    float4 bv = *(const float4*)&bfc[4 * c];
#pragma unroll
    for (int j = 0; j < 8; j++) {
        int row = R + rg + 8 * j;
        if (row < M) {
            float4 o;
            o.x = fmaxf(acc[j][0] + bv.x, 0.f);
            o.y = fmaxf(acc[j][1] + bv.y, 0.f);
            o.z = fmaxf(acc[j][2] + bv.z, 0.f);
            o.w = fmaxf(acc[j][3] + bv.w, 0.f);
            *(float4*)&out[(size_t)row * D + 4 * c] = o;
        }
    }
}

// ---------------------------------------------------------------------------
// Launch
// Inputs: 0 feat_src [100000,128] f32 | 1 feat_dst [50000,128] f32
//         2 W1 [128,256] | 3 b1 [128] | 4 W2 [1,128] | 5 b2 [1]
//         6 Wfc [128,256] | 7 bfc [128] | 8 edge_src [E] i32 | 9 edge_dst [E] i32
// ---------------------------------------------------------------------------
extern "C" void kernel_launch(void* const* d_in, const int* in_sizes, int n_in,
                              void* d_out, int out_size) {
    const float* feat_src = (const float*)d_in[0];
    const float* feat_dst = (const float*)d_in[1];
    const float* W1 = (const float*)d_in[2];
    const float* b1 = (const float*)d_in[3];
    const float* W2 = (const float*)d_in[4];
    const float* Wfc = (const float*)d_in[6];
    const float* bfc = (const float*)d_in[7];
    const int* esrc = (const int*)d_in[8];
    const int* edst = (const int*)d_in[9];
    float* out = (float*)d_out;

    const int n_src = in_sizes[0] / D;
    const int n_dst = in_sizes[1] / D;
    const int E = in_sizes[8];

    const int SMEM = (D * D + 64 * D) * sizeof(float);  // 96 KB
    static bool attr_done = false;
    if (!attr_done) {
        cudaFuncSetAttribute(proj_kernel, cudaFuncAttributeMaxDynamicSharedMemorySize, SMEM);
        cudaFuncSetAttribute(out_kernel, cudaFuncAttributeMaxDynamicSharedMemorySize, SMEM);
        attr_done = true;
    }

    float* a_src;  cudaGetSymbolAddress((void**)&a_src, g_a_src);
    float* a_dst;  cudaGetSymbolAddress((void**)&a_dst, g_a_dst);

    // 1) zero accumulators
    {
        int total = n_dst * (D / 4) + n_dst / 4;
        zero_kernel<<<(total + 255) / 256, 256>>>(n_dst);
    }
    // 2) node projections
    proj_kernel<<<(n_src + 63) / 64, 256, SMEM>>>(feat_src, W1, nullptr, a_src,
                                                  n_src, 2 * D, D);
    proj_kernel<<<(n_dst + 63) / 64, 256, SMEM>>>(feat_dst, W1, b1, a_dst,
                                                  n_dst, 2 * D, 0);
    // 3) edge pass (one warp per edge)
    {
        int wpb = 8;  // 256 threads
        int blocks = (E + wpb - 1) / wpb;
        edge_kernel<<<blocks, 256>>>(esrc, edst, feat_src, W2, E);
    }
    // 4) output GEMM + relu
    out_kernel<<<(n_dst + 63) / 64, 256, SMEM>>>(feat_dst, Wfc, bfc, out, n_dst);
}

// round 3
// speedup vs baseline: 1.9140x; 1.9140x over previous
#include <cuda_runtime.h>
#include <math.h>
#include <stdint.h>

#define D 128
#define MAXSRC 100000
#define MAXDST 50000

// Scratch (allocation-free rule: __device__ globals)
__device__ float g_a_src[MAXSRC * D];   // feat_src @ W1[:,128:256]^T
__device__ float g_a_dst[MAXDST * D];   // feat_dst @ W1[:,0:128]^T + b1
__device__ float g_neigh[MAXDST * D];   // sum_e ex * m   (unnormalized)
__device__ float g_denom[MAXDST];       // sum_e ex

__device__ __forceinline__ unsigned f2tf(float f) {
    unsigned u;
    asm("cvt.rna.tf32.f32 %0, %1;" : "=r"(u) : "f"(f));
    return u;
}

__device__ __forceinline__ float tanh_fast(float x) {
    float y;
    asm("tanh.approx.f32 %0, %1;" : "=f"(y) : "f"(x));
    return y;
}

// ---------------------------------------------------------------------------
// Zero the accumulators (must run every launch; graph replays).
// ---------------------------------------------------------------------------
__global__ void zero_kernel(int ndst) {
    int i = blockIdx.x * blockDim.x + threadIdx.x;
    int n4 = ndst * (D / 4);
    int d4 = ndst / 4;
    float4 z = make_float4(0.f, 0.f, 0.f, 0.f);
    if (i < n4) {
        ((float4*)g_neigh)[i] = z;
    } else if (i < n4 + d4) {
        ((float4*)g_denom)[i - n4] = z;
    }
}

// ---------------------------------------------------------------------------
// TF32 tensor-core GEMM:  Y[m][n] = act( bias[n] + sum_k X[m][k]*W[n][.+k] )
//   N fixed = 128.  K = 128 per phase; optional second phase with X2 =
//   g_neigh normalized by g_denom (fused softmax division).
// Block: 256 thr (8 warps, 2x4 warp grid), tile 128x128, BK=32.
// Smem stride 36 (== 4 mod 32) -> conflict-free mma fragment loads.
// ---------------------------------------------------------------------------
#define BKP 36

__global__ void gemm_tf32(const float* __restrict__ X1,
                          const float* __restrict__ X2,   // null => single phase
                          const float* __restrict__ W, int wstride, int woff,
                          const float* __restrict__ bias,
                          float* __restrict__ Y, int M, int relu) {
    __shared__ unsigned Xs[128 * BKP];
    __shared__ unsigned Ws[128 * BKP];

    const int tid = threadIdx.x;
    const int lane = tid & 31;
    const int warp = tid >> 5;
    const int gid = lane >> 2;     // group id 0..7
    const int tig = lane & 3;      // thread-in-group 0..3
    const int wm = warp >> 2;      // warp row 0..1  -> 64 rows
    const int wn = warp & 3;       // warp col 0..3  -> 32 cols
    const int R = blockIdx.x * 128;

    float acc[4][4][4];
#pragma unroll
    for (int mi = 0; mi < 4; mi++)
#pragma unroll
        for (int ni = 0; ni < 4; ni++)
#pragma unroll
            for (int q = 0; q < 4; q++) acc[mi][ni][q] = 0.f;

    const int nph = X2 ? 2 : 1;
    for (int ph = 0; ph < nph; ph++) {
        const float* Xp = ph ? X2 : X1;
        for (int kc = 0; kc < 128; kc += 32) {
            if (ph | kc) __syncthreads();  // WAR before restaging
            const int wcol = woff + ph * 128 + kc;
            // Stage X tile: 128 rows x 8 float4 slots
            for (int i = tid; i < 128 * 8; i += 256) {
                int r = i >> 3, kq = i & 7;
                int row = R + r;
                float4 v = make_float4(0.f, 0.f, 0.f, 0.f);
                if (row < M) {
                    v = *(const float4*)&Xp[(size_t)row * D + kc + 4 * kq];
                    if (ph) {  // X2 == g_neigh: normalize by denom
                        float dn = g_denom[row];
                        float inv = dn > 0.f ? 1.f / dn : 0.f;
                        v.x *= inv; v.y *= inv; v.z *= inv; v.w *= inv;
                    }
                }
                uint4 t = make_uint4(f2tf(v.x), f2tf(v.y), f2tf(v.z), f2tf(v.w));
                *(uint4*)&Xs[r * BKP + 4 * kq] = t;
            }
            // Stage W tile: 128 n-rows x 8 float4 slots
            for (int i = tid; i < 128 * 8; i += 256) {
                int n = i >> 3, kq = i & 7;
                float4 v = *(const float4*)&W[(size_t)n * wstride + wcol + 4 * kq];
                uint4 t = make_uint4(f2tf(v.x), f2tf(v.y), f2tf(v.z), f2tf(v.w));
                *(uint4*)&Ws[n * BKP + 4 * kq] = t;
            }
            __syncthreads();

#pragma unroll
            for (int k8 = 0; k8 < 4; k8++) {
                unsigned a[4][4], b[4][2];
#pragma unroll
                for (int mi = 0; mi < 4; mi++) {
                    int r0 = (wm * 64 + mi * 16 + gid) * BKP + k8 * 8 + tig;
                    a[mi][0] = Xs[r0];
                    a[mi][1] = Xs[r0 + 8 * BKP];
                    a[mi][2] = Xs[r0 + 4];
                    a[mi][3] = Xs[r0 + 8 * BKP + 4];
                }
#pragma unroll
                for (int ni = 0; ni < 4; ni++) {
                    int n0 = (wn * 32 + ni * 8 + gid) * BKP + k8 * 8 + tig;
                    b[ni][0] = Ws[n0];
                    b[ni][1] = Ws[n0 + 4];
                }
#pragma unroll
                for (int mi = 0; mi < 4; mi++)
#pragma unroll
                    for (int ni = 0; ni < 4; ni++) {
                        asm volatile(
                            "mma.sync.aligned.m16n8k8.row.col.f32.tf32.tf32.f32 "
                            "{%0,%1,%2,%3}, {%4,%5,%6,%7}, {%8,%9}, {%0,%1,%2,%3};"
                            : "+f"(acc[mi][ni][0]), "+f"(acc[mi][ni][1]),
                              "+f"(acc[mi][ni][2]), "+f"(acc[mi][ni][3])
                            : "r"(a[mi][0]), "r"(a[mi][1]), "r"(a[mi][2]),
                              "r"(a[mi][3]), "r"(b[ni][0]), "r"(b[ni][1]));
                    }
            }
        }
    }

    // Epilogue
#pragma unroll
    for (int ni = 0; ni < 4; ni++) {
        int col = wn * 32 + ni * 8 + tig * 2;
        float bx = 0.f, by = 0.f;
        if (bias) { bx = bias[col]; by = bias[col + 1]; }
#pragma unroll
        for (int mi = 0; mi < 4; mi++) {
            int row0 = R + wm * 64 + mi * 16 + gid;
            float2 v0 = make_float2(acc[mi][ni][0] + bx, acc[mi][ni][1] + by);
            float2 v1 = make_float2(acc[mi][ni][2] + bx, acc[mi][ni][3] + by);
            if (relu) {
                v0.x = fmaxf(v0.x, 0.f); v0.y = fmaxf(v0.y, 0.f);
                v1.x = fmaxf(v1.x, 0.f); v1.y = fmaxf(v1.y, 0.f);
            }
            if (row0 < M) *(float2*)&Y[(size_t)row0 * D + col] = v0;
            if (row0 + 8 < M) *(float2*)&Y[(size_t)(row0 + 8) * D + col] = v1;
        }
    }
}

// ---------------------------------------------------------------------------
// Edge pass: one warp per edge.
//   score = W2 . tanh(a_dst[d] + a_src[s]);  ex = exp(score)
//   neigh[d] += ex * feat_src[s];  denom[d] += ex
// ---------------------------------------------------------------------------
__global__ void edge_kernel(const int* __restrict__ esrc,
                            const int* __restrict__ edst,
                            const float* __restrict__ feat_src,
                            const float* __restrict__ W2, int E) {
    __shared__ float w2s[D];
    const int lane = threadIdx.x & 31;
    const int wid = threadIdx.x >> 5;
    if (threadIdx.x < D) w2s[threadIdx.x] = W2[threadIdx.x];
    __syncthreads();

    int e = blockIdx.x * (blockDim.x >> 5) + wid;
    if (e >= E) return;

    const int s = esrc[e];
    const int d = edst[e];
    float4 a = ((const float4*)&g_a_dst[(size_t)d * D])[lane];
    float4 b = ((const float4*)&g_a_src[(size_t)s * D])[lane];
    float z0 = tanh_fast(a.x + b.x);
    float z1 = tanh_fast(a.y + b.y);
    float z2 = tanh_fast(a.z + b.z);
    float z3 = tanh_fast(a.w + b.w);
    float4 w2 = *(float4*)&w2s[4 * lane];
    float p = z0 * w2.x + z1 * w2.y + z2 * w2.z + z3 * w2.w;
#pragma unroll
    for (int o = 16; o > 0; o >>= 1) p += __shfl_xor_sync(0xFFFFFFFFu, p, o);
    float ex = __expf(p);

    float4 m = ((const float4*)&feat_src[(size_t)s * D])[lane];
    float* np = &g_neigh[(size_t)d * D + 4 * lane];
    asm volatile("red.global.add.v4.f32 [%0], {%1,%2,%3,%4};" ::"l"(np),
                 "f"(ex * m.x), "f"(ex * m.y), "f"(ex * m.z), "f"(ex * m.w)
                 : "memory");
    if (lane == 0) atomicAdd(&g_denom[d], ex);
}

// ---------------------------------------------------------------------------
// Launch
// Inputs: 0 feat_src [100000,128] f32 | 1 feat_dst [50000,128] f32
//         2 W1 [128,256] | 3 b1 [128] | 4 W2 [1,128] | 5 b2 [1]
//         6 Wfc [128,256] | 7 bfc [128] | 8 edge_src [E] i32 | 9 edge_dst [E] i32
// ---------------------------------------------------------------------------
extern "C" void kernel_launch(void* const* d_in, const int* in_sizes, int n_in,
                              void* d_out, int out_size) {
    const float* feat_src = (const float*)d_in[0];
    const float* feat_dst = (const float*)d_in[1];
    const float* W1 = (const float*)d_in[2];
    const float* b1 = (const float*)d_in[3];
    const float* W2 = (const float*)d_in[4];
    const float* Wfc = (const float*)d_in[6];
    const float* bfc = (const float*)d_in[7];
    const int* esrc = (const int*)d_in[8];
    const int* edst = (const int*)d_in[9];
    float* out = (float*)d_out;

    const int n_src = in_sizes[0] / D;
    const int n_dst = in_sizes[1] / D;
    const int E = in_sizes[8];

    float* a_src;  cudaGetSymbolAddress((void**)&a_src, g_a_src);
    float* a_dst;  cudaGetSymbolAddress((void**)&a_dst, g_a_dst);
    float* neigh;  cudaGetSymbolAddress((void**)&neigh, g_neigh);

    // 1) zero accumulators
    {
        int total = n_dst * (D / 4) + n_dst / 4;
        zero_kernel<<<(total + 255) / 256, 256>>>(n_dst);
    }
    // 2) node projections (tf32 tensor cores)
    gemm_tf32<<<(n_src + 127) / 128, 256>>>(feat_src, nullptr, W1, 2 * D, D,
                                            nullptr, a_src, n_src, 0);
    gemm_tf32<<<(n_dst + 127) / 128, 256>>>(feat_dst, nullptr, W1, 2 * D, 0,
                                            b1, a_dst, n_dst, 0);
    // 3) edge pass (one warp per edge)
    {
        int wpb = 8;  // 256 threads
        int blocks = (E + wpb - 1) / wpb;
        edge_kernel<<<blocks, 256>>>(esrc, edst, feat_src, W2, E);
    }
    // 4) output GEMM + relu (K=256 via two phases, denom-normalize fused)
    gemm_tf32<<<(n_dst + 127) / 128, 256>>>(feat_dst, neigh, Wfc, 2 * D, 0,
                                            bfc, out, n_dst, 1);
}

// round 4
// speedup vs baseline: 2.1596x; 1.1283x over previous
#include <cuda_runtime.h>
#include <cuda_fp16.h>
#include <math.h>
#include <stdint.h>

#define D 128
#define MAXSRC 100000
#define MAXDST 50000

// Scratch (allocation-free rule: __device__ globals)
__device__ __half g_a_srch[MAXSRC * D];  // feat_src @ W1[:,128:256]^T   (fp16)
__device__ __half g_a_dsth[MAXDST * D];  // feat_dst @ W1[:,0:128]^T + b1 (fp16)
__device__ __half g_msrc[MAXSRC * D];    // fp16 copy of feat_src (gathered as m)
__device__ float g_neigh[MAXDST * D];    // sum_e ex * m (fp32 atomics)
__device__ float g_denom[MAXDST];        // sum_e ex

__device__ __forceinline__ unsigned f2tf(float f) {
    unsigned u;
    asm("cvt.rna.tf32.f32 %0, %1;" : "=r"(u) : "f"(f));
    return u;
}
__device__ __forceinline__ float tanh_fast(float x) {
    float y;
    asm("tanh.approx.f32 %0, %1;" : "=f"(y) : "f"(x));
    return y;
}
__device__ __forceinline__ uint2 f4_to_h4(float4 v) {
    __half2 lo = __floats2half2_rn(v.x, v.y);
    __half2 hi = __floats2half2_rn(v.z, v.w);
    uint2 r;
    r.x = *(unsigned*)&lo;
    r.y = *(unsigned*)&hi;
    return r;
}

// ---------------------------------------------------------------------------
// Zero accumulators (graph replays -> must run every launch)
// ---------------------------------------------------------------------------
__global__ void zero_kernel(int ndst) {
    int i = blockIdx.x * blockDim.x + threadIdx.x;
    int n4 = ndst * (D / 4);
    int d4 = ndst / 4;
    float4 z = make_float4(0.f, 0.f, 0.f, 0.f);
    if (i < n4) {
        ((float4*)g_neigh)[i] = z;
    } else if (i < n4 + d4) {
        ((float4*)g_denom)[i - n4] = z;
    }
}

// ---------------------------------------------------------------------------
// FP16 tensor-core projection GEMM: Yh[m][n] = half( bias[n] + X[m]@W[n] )
//   Tile 128x128, BK=32, 8 warps (2x4). Smem stride 40 halves (conflict-free).
//   Optionally writes fp16 copy of staged X to msrc (fused feat_src cast).
// ---------------------------------------------------------------------------
#define HS 40  // half-stride: 32 + 8 pad

__global__ void proj_fp16(const float* __restrict__ X,
                          const float* __restrict__ W, int wstride, int woff,
                          const float* __restrict__ bias,
                          __half* __restrict__ Y, __half* __restrict__ msrc,
                          int M) {
    __shared__ __half Xh[128 * HS];
    __shared__ __half Wh[128 * HS];

    const int tid = threadIdx.x;
    const int lane = tid & 31;
    const int warp = tid >> 5;
    const int gid = lane >> 2;
    const int tig = lane & 3;
    const int wm = warp >> 2;  // 0..1 -> 64 rows
    const int wn = warp & 3;   // 0..3 -> 32 cols
    const int R = blockIdx.x * 128;

    float acc[4][4][4];
#pragma unroll
    for (int mi = 0; mi < 4; mi++)
#pragma unroll
        for (int ni = 0; ni < 4; ni++)
#pragma unroll
            for (int q = 0; q < 4; q++) acc[mi][ni][q] = 0.f;

    for (int kc = 0; kc < 128; kc += 32) {
        if (kc) __syncthreads();
        // Stage X tile (and fused fp16 export of feat_src)
        for (int i = tid; i < 128 * 8; i += 256) {
            int r = i >> 3, kq = i & 7;
            int row = R + r;
            float4 v = make_float4(0.f, 0.f, 0.f, 0.f);
            if (row < M) v = *(const float4*)&X[(size_t)row * D + kc + 4 * kq];
            uint2 h = f4_to_h4(v);
            *(uint2*)&Xh[r * HS + 4 * kq] = h;
            if (msrc && row < M)
                *(uint2*)&msrc[(size_t)row * D + kc + 4 * kq] = h;
        }
        // Stage W tile
        for (int i = tid; i < 128 * 8; i += 256) {
            int n = i >> 3, kq = i & 7;
            float4 v = *(const float4*)&W[(size_t)n * wstride + woff + kc + 4 * kq];
            *(uint2*)&Wh[n * HS + 4 * kq] = f4_to_h4(v);
        }
        __syncthreads();

#pragma unroll
        for (int k16 = 0; k16 < 32; k16 += 16) {
            unsigned a[4][4], b[4][2];
#pragma unroll
            for (int mi = 0; mi < 4; mi++) {
                int r0 = (wm * 64 + mi * 16 + gid) * HS + k16 + 2 * tig;
                a[mi][0] = *(unsigned*)&Xh[r0];
                a[mi][1] = *(unsigned*)&Xh[r0 + 8 * HS];
                a[mi][2] = *(unsigned*)&Xh[r0 + 8];
                a[mi][3] = *(unsigned*)&Xh[r0 + 8 * HS + 8];
            }
#pragma unroll
            for (int ni = 0; ni < 4; ni++) {
                int n0 = (wn * 32 + ni * 8 + gid) * HS + k16 + 2 * tig;
                b[ni][0] = *(unsigned*)&Wh[n0];
                b[ni][1] = *(unsigned*)&Wh[n0 + 8];
            }
#pragma unroll
            for (int mi = 0; mi < 4; mi++)
#pragma unroll
                for (int ni = 0; ni < 4; ni++) {
                    asm volatile(
                        "mma.sync.aligned.m16n8k16.row.col.f32.f16.f16.f32 "
                        "{%0,%1,%2,%3}, {%4,%5,%6,%7}, {%8,%9}, {%0,%1,%2,%3};"
                        : "+f"(acc[mi][ni][0]), "+f"(acc[mi][ni][1]),
                          "+f"(acc[mi][ni][2]), "+f"(acc[mi][ni][3])
                        : "r"(a[mi][0]), "r"(a[mi][1]), "r"(a[mi][2]),
                          "r"(a[mi][3]), "r"(b[ni][0]), "r"(b[ni][1]));
                }
        }
    }

    // Epilogue: bias add in fp32, store half2
#pragma unroll
    for (int ni = 0; ni < 4; ni++) {
        int col = wn * 32 + ni * 8 + 2 * tig;
        float bx = 0.f, by = 0.f;
        if (bias) { bx = bias[col]; by = bias[col + 1]; }
#pragma unroll
        for (int mi = 0; mi < 4; mi++) {
            int row0 = R + wm * 64 + mi * 16 + gid;
            if (row0 < M)
                *(__half2*)&Y[(size_t)row0 * D + col] =
                    __floats2half2_rn(acc[mi][ni][0] + bx, acc[mi][ni][1] + by);
            if (row0 + 8 < M)
                *(__half2*)&Y[(size_t)(row0 + 8) * D + col] =
                    __floats2half2_rn(acc[mi][ni][2] + bx, acc[mi][ni][3] + by);
        }
    }
}

// ---------------------------------------------------------------------------
// TF32 out GEMM: out = relu(bfc + [feat_dst | neigh/denom] @ Wfc^T)
// ---------------------------------------------------------------------------
#define BKP 36

__global__ void gemm_tf32(const float* __restrict__ X1,
                          const float* __restrict__ X2,
                          const float* __restrict__ W, int wstride, int woff,
                          const float* __restrict__ bias,
                          float* __restrict__ Y, int M, int relu) {
    __shared__ unsigned Xs[128 * BKP];
    __shared__ unsigned Ws[128 * BKP];

    const int tid = threadIdx.x;
    const int lane = tid & 31;
    const int warp = tid >> 5;
    const int gid = lane >> 2;
    const int tig = lane & 3;
    const int wm = warp >> 2;
    const int wn = warp & 3;
    const int R = blockIdx.x * 128;

    float acc[4][4][4];
#pragma unroll
    for (int mi = 0; mi < 4; mi++)
#pragma unroll
        for (int ni = 0; ni < 4; ni++)
#pragma unroll
            for (int q = 0; q < 4; q++) acc[mi][ni][q] = 0.f;

    const int nph = X2 ? 2 : 1;
    for (int ph = 0; ph < nph; ph++) {
        const float* Xp = ph ? X2 : X1;
        for (int kc = 0; kc < 128; kc += 32) {
            if (ph | kc) __syncthreads();
            const int wcol = woff + ph * 128 + kc;
            for (int i = tid; i < 128 * 8; i += 256) {
                int r = i >> 3, kq = i & 7;
                int row = R + r;
                float4 v = make_float4(0.f, 0.f, 0.f, 0.f);
                if (row < M) {
                    v = *(const float4*)&Xp[(size_t)row * D + kc + 4 * kq];
                    if (ph) {
                        float dn = g_denom[row];
                        float inv = dn > 0.f ? 1.f / dn : 0.f;
                        v.x *= inv; v.y *= inv; v.z *= inv; v.w *= inv;
                    }
                }
                uint4 t = make_uint4(f2tf(v.x), f2tf(v.y), f2tf(v.z), f2tf(v.w));
                *(uint4*)&Xs[r * BKP + 4 * kq] = t;
            }
            for (int i = tid; i < 128 * 8; i += 256) {
                int n = i >> 3, kq = i & 7;
                float4 v = *(const float4*)&W[(size_t)n * wstride + wcol + 4 * kq];
                uint4 t = make_uint4(f2tf(v.x), f2tf(v.y), f2tf(v.z), f2tf(v.w));
                *(uint4*)&Ws[n * BKP + 4 * kq] = t;
            }
            __syncthreads();

#pragma unroll
            for (int k8 = 0; k8 < 4; k8++) {
                unsigned a[4][4], b[4][2];
#pragma unroll
                for (int mi = 0; mi < 4; mi++) {
                    int r0 = (wm * 64 + mi * 16 + gid) * BKP + k8 * 8 + tig;
                    a[mi][0] = Xs[r0];
                    a[mi][1] = Xs[r0 + 8 * BKP];
                    a[mi][2] = Xs[r0 + 4];
                    a[mi][3] = Xs[r0 + 8 * BKP + 4];
                }
#pragma unroll
                for (int ni = 0; ni < 4; ni++) {
                    int n0 = (wn * 32 + ni * 8 + gid) * BKP + k8 * 8 + tig;
                    b[ni][0] = Ws[n0];
                    b[ni][1] = Ws[n0 + 4];
                }
#pragma unroll
                for (int mi = 0; mi < 4; mi++)
#pragma unroll
                    for (int ni = 0; ni < 4; ni++) {
                        asm volatile(
                            "mma.sync.aligned.m16n8k8.row.col.f32.tf32.tf32.f32 "
                            "{%0,%1,%2,%3}, {%4,%5,%6,%7}, {%8,%9}, {%0,%1,%2,%3};"
                            : "+f"(acc[mi][ni][0]), "+f"(acc[mi][ni][1]),
                              "+f"(acc[mi][ni][2]), "+f"(acc[mi][ni][3])
                            : "r"(a[mi][0]), "r"(a[mi][1]), "r"(a[mi][2]),
                              "r"(a[mi][3]), "r"(b[ni][0]), "r"(b[ni][1]));
                    }
            }
        }
    }

#pragma unroll
    for (int ni = 0; ni < 4; ni++) {
        int col = wn * 32 + ni * 8 + tig * 2;
        float bx = 0.f, by = 0.f;
        if (bias) { bx = bias[col]; by = bias[col + 1]; }
#pragma unroll
        for (int mi = 0; mi < 4; mi++) {
            int row0 = R + wm * 64 + mi * 16 + gid;
            float2 v0 = make_float2(acc[mi][ni][0] + bx, acc[mi][ni][1] + by);
            float2 v1 = make_float2(acc[mi][ni][2] + bx, acc[mi][ni][3] + by);
            if (relu) {
                v0.x = fmaxf(v0.x, 0.f); v0.y = fmaxf(v0.y, 0.f);
                v1.x = fmaxf(v1.x, 0.f); v1.y = fmaxf(v1.y, 0.f);
            }
            if (row0 < M) *(float2*)&Y[(size_t)row0 * D + col] = v0;
            if (row0 + 8 < M) *(float2*)&Y[(size_t)(row0 + 8) * D + col] = v1;
        }
    }
}

// ---------------------------------------------------------------------------
// Edge pass: one warp per edge, fp16 gathers (8B/lane), fp32 math + atomics.
// ---------------------------------------------------------------------------
__global__ void edge_kernel(const int* __restrict__ esrc,
                            const int* __restrict__ edst,
                            const float* __restrict__ W2, int E) {
    __shared__ float w2s[D];
    const int lane = threadIdx.x & 31;
    const int wid = threadIdx.x >> 5;
    if (threadIdx.x < D) w2s[threadIdx.x] = W2[threadIdx.x];
    __syncthreads();

    int e = blockIdx.x * (blockDim.x >> 5) + wid;
    if (e >= E) return;

    const int s = esrc[e];
    const int d = edst[e];
    uint2 ua = ((const uint2*)(g_a_dsth + (size_t)d * D))[lane];
    uint2 ub = ((const uint2*)(g_a_srch + (size_t)s * D))[lane];
    float2 a01 = __half22float2(*(__half2*)&ua.x);
    float2 a23 = __half22float2(*(__half2*)&ua.y);
    float2 b01 = __half22float2(*(__half2*)&ub.x);
    float2 b23 = __half22float2(*(__half2*)&ub.y);
    float z0 = tanh_fast(a01.x + b01.x);
    float z1 = tanh_fast(a01.y + b01.y);
    float z2 = tanh_fast(a23.x + b23.x);
    float z3 = tanh_fast(a23.y + b23.y);
    float4 w2 = *(float4*)&w2s[4 * lane];
    float p = z0 * w2.x + z1 * w2.y + z2 * w2.z + z3 * w2.w;
#pragma unroll
    for (int o = 16; o > 0; o >>= 1) p += __shfl_xor_sync(0xFFFFFFFFu, p, o);
    float ex = __expf(p);

    uint2 um = ((const uint2*)(g_msrc + (size_t)s * D))[lane];
    float2 m01 = __half22float2(*(__half2*)&um.x);
    float2 m23 = __half22float2(*(__half2*)&um.y);
    float* np = &g_neigh[(size_t)d * D + 4 * lane];
    asm volatile("red.global.add.v4.f32 [%0], {%1,%2,%3,%4};" ::"l"(np),
                 "f"(ex * m01.x), "f"(ex * m01.y), "f"(ex * m23.x),
                 "f"(ex * m23.y)
                 : "memory");
    if (lane == 0) atomicAdd(&g_denom[d], ex);
}

// ---------------------------------------------------------------------------
// Launch
// Inputs: 0 feat_src [100000,128] f32 | 1 feat_dst [50000,128] f32
//         2 W1 [128,256] | 3 b1 [128] | 4 W2 [1,128] | 5 b2 [1]
//         6 Wfc [128,256] | 7 bfc [128] | 8 edge_src [E] i32 | 9 edge_dst [E] i32
// ---------------------------------------------------------------------------
extern "C" void kernel_launch(void* const* d_in, const int* in_sizes, int n_in,
                              void* d_out, int out_size) {
    const float* feat_src = (const float*)d_in[0];
    const float* feat_dst = (const float*)d_in[1];
    const float* W1 = (const float*)d_in[2];
    const float* b1 = (const float*)d_in[3];
    const float* W2 = (const float*)d_in[4];
    const float* Wfc = (const float*)d_in[6];
    const float* bfc = (const float*)d_in[7];
    const int* esrc = (const int*)d_in[8];
    const int* edst = (const int*)d_in[9];
    float* out = (float*)d_out;

    const int n_src = in_sizes[0] / D;
    const int n_dst = in_sizes[1] / D;
    const int E = in_sizes[8];

    __half* a_srch; cudaGetSymbolAddress((void**)&a_srch, g_a_srch);
    __half* a_dsth; cudaGetSymbolAddress((void**)&a_dsth, g_a_dsth);
    __half* msrc;   cudaGetSymbolAddress((void**)&msrc, g_msrc);
    float* neigh;   cudaGetSymbolAddress((void**)&neigh, g_neigh);

    // 1) zero accumulators
    {
        int total = n_dst * (D / 4) + n_dst / 4;
        zero_kernel<<<(total + 255) / 256, 256>>>(n_dst);
    }
    // 2) node projections (fp16 HMMA); src variant also exports fp16 feat_src
    proj_fp16<<<(n_src + 127) / 128, 256>>>(feat_src, W1, 2 * D, D, nullptr,
                                            a_srch, msrc, n_src);
    proj_fp16<<<(n_dst + 127) / 128, 256>>>(feat_dst, W1, 2 * D, 0, b1,
                                            a_dsth, nullptr, n_dst);
    // 3) edge pass (one warp per edge)
    {
        int wpb = 8;  // 256 threads
        int blocks = (E + wpb - 1) / wpb;
        edge_kernel<<<blocks, 256>>>(esrc, edst, W2, E);
    }
    // 4) output GEMM + relu (tf32, K=256 two-phase, denom-normalize fused)
    gemm_tf32<<<(n_dst + 127) / 128, 256>>>(feat_dst, neigh, Wfc, 2 * D, 0,
                                            bfc, out, n_dst, 1);
}